// round 14
// baseline (speedup 1.0000x reference)
#include <cuda_runtime.h>

#define HLOG2E 0.7213475204444817f   // log2(e)/2
#define EPS    1e-8f

__device__ float        g_partials[8192];
__device__ unsigned int g_done;   // zero-init; last CTA resets -> graph-replay safe

__device__ __forceinline__ float ex2a(float x) {
    float r; asm("ex2.approx.ftz.f32 %0, %1;" : "=f"(r) : "f"(x)); return r;
}
__device__ __forceinline__ float lg2a(float x) {
    float r; asm("lg2.approx.ftz.f32 %0, %1;" : "=f"(r) : "f"(x)); return r;
}

// Pair identity: log2(sig(d)) + log2(sig(-d)) = -2*lg2(e^{d/2} + e^{-d/2}).
// Q = e^{s/2}, R = 1/Q; v_ij = Qi*Rj + Ri*Qj. Gains prescaled by 2 so the
// folded contribution of unordered pair {i,j} is -|g2i-g2j| * lg2(v_ij).
//
// Docs are counting-sorted by relevance class in smem. Equal-class pairs have
// |g2i-g2j| = 0 and are skipped. For thread at sorted position t (class a):
//   lower run j in [0, bA):   g2j < g2  ->  sum += g2*l - g2j*l   (linear!)
//   upper run j in [bB, L):   g2j > g2  ->  sum += g2j*l - g2*l
// Each unordered pair is assigned to exactly one endpoint by position parity:
// t takes lower-run j with (t+j) odd, upper-run j with (t+j) even.

__global__ void __launch_bounds__(128, 12) ndcg_kernel(
    const float* __restrict__ scores,
    const int*   __restrict__ relev,
    const int*   __restrict__ qlen,
    float*       __restrict__ out,
    int D, int B)
{
    const int b = blockIdx.x;
    const int i = threadIdx.x;          // 0..127 = D
    const int lane = i & 31;
    const int w    = i >> 5;

    __shared__ float4 s_d[128];         // sorted (Q, R, 2*gain, 0)
    __shared__ int    s_wc[4][8];       // per-warp class counts
    __shared__ float  s_rn[4], s_ri[4];
    __shared__ int    s_last;

    const int  L     = qlen[b];
    const bool valid = (i < L);

    const float sc  = scores[b * D + i];
    const int   rv0 = relev[b * D + i];
    const int   rv  = valid ? rv0 : 5;            // invalid docs -> bucket 5

    const float Q  = ex2a(sc * HLOG2E);           // e^{s/2}
    const float R  = ex2a(sc * (-HLOG2E));        // e^{-s/2}
    const float g2 = (float)(2 * ((1 << rv0) - 1));   // used only if valid

    if (i < 32) s_wc[i >> 3][i & 7] = 0;
    __syncthreads();

    // deterministic counting-sort rank: warp-local match + per-warp counts
    const unsigned mmask = __match_any_sync(0xFFFFFFFFu, rv);
    const int rwarp = __popc(mmask & ((1u << lane) - 1u));
    if (rwarp == 0) s_wc[w][rv] = __popc(mmask);
    __syncthreads();

    int cnt0 = s_wc[0][0] + s_wc[1][0] + s_wc[2][0] + s_wc[3][0];
    int cnt1 = s_wc[0][1] + s_wc[1][1] + s_wc[2][1] + s_wc[3][1];
    int cnt2 = s_wc[0][2] + s_wc[1][2] + s_wc[2][2] + s_wc[3][2];
    int cnt3 = s_wc[0][3] + s_wc[1][3] + s_wc[2][3] + s_wc[3][3];
    int cnt4 = s_wc[0][4] + s_wc[1][4] + s_wc[2][4] + s_wc[3][4];
    const int off1 = cnt0, off2 = off1 + cnt1, off3 = off2 + cnt2, off4 = off3 + cnt3;

    int t = 0, bA = 0, bB = 0;
    if (valid) {
        const int offa = (rv == 0) ? 0 : (rv == 1) ? off1 : (rv == 2) ? off2
                        : (rv == 3) ? off3 : off4;
        const int cnta = (rv == 0) ? cnt0 : (rv == 1) ? cnt1 : (rv == 2) ? cnt2
                        : (rv == 3) ? cnt3 : cnt4;
        int pre = 0;
        if (w > 0) pre += s_wc[0][rv];
        if (w > 1) pre += s_wc[1][rv];
        if (w > 2) pre += s_wc[2][rv];
        t  = offa + pre + rwarp;
        bA = offa;
        bB = offa + cnta;
        s_d[t] = make_float4(Q, R, g2, 0.0f);
    }
    __syncthreads();

    // ---- pairwise sum over cross-class pairs (linear in g2j per run) ----
    float pos = 0.0f;          // = sum |g2i-g2j| * lg2(v)  (>= 0)
    if (valid) {
        float S0 = 0.0f, T0 = 0.0f, S1 = 0.0f, T1 = 0.0f;
        // lower run: j parity != t parity
        {
            int j = (t & 1) ^ 1;
            for (; j + 2 < bA; j += 4) {
                const float4 p0 = s_d[j];
                const float4 p1 = s_d[j + 2];
                const float  v0 = fmaf(Q, p0.y, R * p0.x);
                const float  v1 = fmaf(Q, p1.y, R * p1.x);
                const float  l0 = lg2a(v0);
                const float  l1 = lg2a(v1);
                T0 += l0;  S0 = fmaf(p0.z, l0, S0);
                T1 += l1;  S1 = fmaf(p1.z, l1, S1);
            }
            for (; j < bA; j += 2) {
                const float4 p0 = s_d[j];
                const float  v0 = fmaf(Q, p0.y, R * p0.x);
                const float  l0 = lg2a(v0);
                T0 += l0;  S0 = fmaf(p0.z, l0, S0);
            }
            // lower: sum (g2 - g2j) * l = g2*T - S
            pos += fmaf(g2, T0 + T1, -(S0 + S1));
        }
        // upper run: j parity == t parity
        {
            S0 = 0.0f; T0 = 0.0f; S1 = 0.0f; T1 = 0.0f;
            int j = bB + ((bB ^ t) & 1);
            for (; j + 2 < L; j += 4) {
                const float4 p0 = s_d[j];
                const float4 p1 = s_d[j + 2];
                const float  v0 = fmaf(Q, p0.y, R * p0.x);
                const float  v1 = fmaf(Q, p1.y, R * p1.x);
                const float  l0 = lg2a(v0);
                const float  l1 = lg2a(v1);
                T0 += l0;  S0 = fmaf(p0.z, l0, S0);
                T1 += l1;  S1 = fmaf(p1.z, l1, S1);
            }
            for (; j < L; j += 2) {
                const float4 p0 = s_d[j];
                const float  v0 = fmaf(Q, p0.y, R * p0.x);
                const float  l0 = lg2a(v0);
                T0 += l0;  S0 = fmaf(p0.z, l0, S0);
            }
            // upper: sum (g2j - g2) * l = S - g2*T
            pos += fmaf(-g2, T0 + T1, S0 + S1);
        }
    }

    // ---- ideal DCG via counting sort (gains in {0,1,3,7,15}) ----
    float idl = 0.0f;
    if (valid) {
        const int c4 = cnt4;
        const int c3 = c4 + cnt3;
        const int c2 = c3 + cnt2;
        const int c1 = c2 + cnt1;
        float gr;
        if      (i < c4) gr = 15.0f;
        else if (i < c3) gr = 7.0f;
        else if (i < c2) gr = 3.0f;
        else if (i < c1) gr = 1.0f;
        else             gr = 0.0f;
        idl = __fdividef(gr, lg2a((float)(i + 2)));
    }

    // ---- block reduction of (pos, idl) ----
    #pragma unroll
    for (int off = 16; off > 0; off >>= 1) {
        pos += __shfl_down_sync(0xFFFFFFFFu, pos, off);
        idl += __shfl_down_sync(0xFFFFFFFFu, idl, off);
    }
    if (lane == 0) { s_rn[w] = pos; s_ri[w] = idl; }
    __syncthreads();
    if (i == 0) {
        const float n  = (s_rn[0] + s_rn[1]) + (s_rn[2] + s_rn[3]);
        const float id = (s_ri[0] + s_ri[1]) + (s_ri[2] + s_ri[3]);
        g_partials[b] = n / (id + EPS);   // = -num/(idcg+eps), num = -n
        __threadfence();
        const unsigned int tk = atomicAdd(&g_done, 1u);
        s_last = (tk == (unsigned int)(gridDim.x - 1));
    }
    __syncthreads();

    // ---- last CTA: deterministic final reduction ----
    if (s_last) {
        __threadfence();
        float s = 0.0f;
        for (int r = i; r < B; r += 128) s += g_partials[r];
        #pragma unroll
        for (int off = 16; off > 0; off >>= 1)
            s += __shfl_down_sync(0xFFFFFFFFu, s, off);
        if (lane == 0) s_rn[w] = s;
        __syncthreads();
        if (i == 0) {
            out[0] = ((s_rn[0] + s_rn[1]) + (s_rn[2] + s_rn[3])) / (float)B;
            g_done = 0;   // reset for next graph replay
        }
    }
}

extern "C" void kernel_launch(void* const* d_in, const int* in_sizes, int n_in,
                              void* d_out, int out_size)
{
    const float* scores = (const float*)d_in[0];
    const int*   relev  = (const int*)  d_in[1];
    const int*   qlen   = (const int*)  d_in[2];
    float*       out    = (float*)      d_out;

    const int B = in_sizes[2];
    const int D = in_sizes[0] / B;   // 128

    ndcg_kernel<<<B, 128>>>(scores, relev, qlen, out, D, B);
}

// round 15
// speedup vs baseline: 1.1932x; 1.1932x over previous
#include <cuda_runtime.h>

#define HLOG2E 0.7213475204444817f   // log2(e)/2
#define EPS    1e-8f

__device__ float        g_num[2][8192];   // [parity][row]; unwritten slots stay 0
__device__ float        g_idl[8192];
__device__ unsigned int g_done;           // zero-init; last CTA resets (replay safe)

__device__ __forceinline__ float ex2a(float x) {
    float r; asm("ex2.approx.ftz.f32 %0, %1;" : "=f"(r) : "f"(x)); return r;
}
__device__ __forceinline__ float lg2a(float x) {
    float r; asm("lg2.approx.ftz.f32 %0, %1;" : "=f"(r) : "f"(x)); return r;
}

// Pair identity: log2(sig(d)) + log2(sig(-d)) = -2*lg2(e^{d/2} + e^{-d/2}).
// Q = e^{s/2}, R = 1/Q; v_ij = Qi*Rj + Ri*Qj. Gains prescaled by 2, so the
// folded contribution of unordered pair {i,j} is -|g2i-g2j| * lg2(v_ij).
//
// Grid = 2B. CTA (b, h=bid&1): short rows (L<=64) handled entirely by h=0
// (h=1 exits early); long rows split by k-parity so every CTA runs <= 32
// serial iterations -> per-SM makespan halves, multi-wave refill balances.
__global__ void __launch_bounds__(128, 12) ndcg_kernel(
    const float* __restrict__ scores,
    const int*   __restrict__ relev,
    const int*   __restrict__ qlen,
    float*       __restrict__ out,
    int D, int B)
{
    const int bid = blockIdx.x;
    const int b   = bid >> 1;
    const int h   = bid & 1;
    const int i   = threadIdx.x;        // 0..127 = D

    __shared__ float2 s_QR[192];
    __shared__ float  s_g2[192];
    __shared__ int    s_cnt[8];
    __shared__ float  s_rn[4], s_ri[4];
    __shared__ int    s_last;

    const int  L       = qlen[b];
    const bool longrow = (L > 64);
    const bool active  = (h == 0) || longrow;

    if (active) {
        const bool valid = (i < L);

        const float sc = scores[b * D + i];
        const int   rv = relev[b * D + i];
        const float Q  = ex2a(sc * HLOG2E);       // e^{s/2}
        const float R  = ex2a(sc * (-HLOG2E));    // e^{-s/2}
        const float g2 = valid ? (float)(2 * ((1 << rv) - 1)) : 0.0f;

        const float2 qr = make_float2(Q, R);
        if (h == 0 && i < 8) s_cnt[i] = 0;
        if (valid)  { s_QR[i] = qr;     s_g2[i] = g2; }     // primary
        if (i < 64) { s_QR[L + i] = qr; s_g2[L + i] = g2; } // mirror [L, L+63]
        __syncthreads();
        if (h == 0 && valid) atomicAdd(&s_cnt[rv], 1);
        __syncthreads();

        // ---- this CTA's share of the pairwise sum (2 chains) ----
        // short row (h=0 only): k = 1..halfm step 1
        // long  row:            k = 1+h..halfm step 2
        float num = 0.0f;
        if (valid && L > 1) {
            const int     halfm = (L - 1) >> 1;
            const int     kstep = longrow ? 2 : 1;
            const float2* bq = &s_QR[i];
            const float*  bg = &s_g2[i];
            float n0 = 0.0f, n1 = 0.0f;

            int k = longrow ? (1 + h) : 1;
            for (; k + kstep <= halfm; k += 2 * kstep) {
                const float2 p0 = bq[k];
                const float2 p1 = bq[k + kstep];
                const float  v0 = fmaf(Q, p0.y, R * p0.x);   // Qi*Rj + Ri*Qj
                const float  v1 = fmaf(Q, p1.y, R * p1.x);
                const float  l0 = lg2a(v0);                  // MUFU.LG2
                const float  l1 = lg2a(v1);
                const float  d0 = g2 - bg[k];
                const float  d1 = g2 - bg[k + kstep];
                n0 = fmaf(-fabsf(d0), l0, n0);
                n1 = fmaf(-fabsf(d1), l1, n1);
            }
            if (k <= halfm) {
                const float2 p0 = bq[k];
                const float  v0 = fmaf(Q, p0.y, R * p0.x);
                n0 = fmaf(-fabsf(g2 - bg[k]), lg2a(v0), n0);
            }
            // tie distance k = L/2 (L even), counted once by i < L/2:
            // short row -> h=0 CTA; long row -> h=1 CTA
            if (((L & 1) == 0) && (i < (L >> 1)) && (h == (longrow ? 1 : 0))) {
                const int    m  = L >> 1;
                const float2 p0 = s_QR[i + m];
                const float  v0 = fmaf(Q, p0.y, R * p0.x);
                n1 = fmaf(-fabsf(g2 - s_g2[i + m]), lg2a(v0), n1);
            }
            num = n0 + n1;
        }

        // ---- ideal DCG via counting sort (h=0 only; gains in {0,1,3,7,15}) ----
        float idl = 0.0f;
        if (h == 0 && valid) {
            const int c4 = s_cnt[4];
            const int c3 = c4 + s_cnt[3];
            const int c2 = c3 + s_cnt[2];
            const int c1 = c2 + s_cnt[1];
            float gr;
            if      (i < c4) gr = 15.0f;
            else if (i < c3) gr = 7.0f;
            else if (i < c2) gr = 3.0f;
            else if (i < c1) gr = 1.0f;
            else             gr = 0.0f;
            idl = __fdividef(gr, lg2a((float)(i + 2)));
        }

        // ---- block reduction of (num, idl) ----
        #pragma unroll
        for (int off = 16; off > 0; off >>= 1) {
            num += __shfl_down_sync(0xFFFFFFFFu, num, off);
            idl += __shfl_down_sync(0xFFFFFFFFu, idl, off);
        }
        const int wid  = i >> 5;
        const int lane = i & 31;
        if (lane == 0) { s_rn[wid] = num; s_ri[wid] = idl; }
        __syncthreads();
        if (i == 0) {
            g_num[h][b] = (s_rn[0] + s_rn[1]) + (s_rn[2] + s_rn[3]);
            if (h == 0)
                g_idl[b] = (s_ri[0] + s_ri[1]) + (s_ri[2] + s_ri[3]);
        }
    }

    // ---- completion + fused deterministic final reduction ----
    __syncthreads();
    if (threadIdx.x == 0) {
        __threadfence();
        const unsigned int t = atomicAdd(&g_done, 1u);
        s_last = (t == (unsigned int)(gridDim.x - 1));
    }
    __syncthreads();

    if (s_last) {
        __threadfence();
        float s = 0.0f;
        for (int r = i; r < B; r += 128) {
            const float n = g_num[0][r] + g_num[1][r];
            s += __fdividef(-n, g_idl[r] + EPS);
        }
        #pragma unroll
        for (int off = 16; off > 0; off >>= 1)
            s += __shfl_down_sync(0xFFFFFFFFu, s, off);
        const int wid  = i >> 5;
        const int lane = i & 31;
        if (lane == 0) s_rn[wid] = s;
        __syncthreads();
        if (i == 0) {
            out[0] = ((s_rn[0] + s_rn[1]) + (s_rn[2] + s_rn[3])) / (float)B;
            g_done = 0;   // reset for next graph replay
        }
    }
}

extern "C" void kernel_launch(void* const* d_in, const int* in_sizes, int n_in,
                              void* d_out, int out_size)
{
    const float* scores = (const float*)d_in[0];
    const int*   relev  = (const int*)  d_in[1];
    const int*   qlen   = (const int*)  d_in[2];
    float*       out    = (float*)      d_out;

    const int B = in_sizes[2];
    const int D = in_sizes[0] / B;   // 128

    ndcg_kernel<<<2 * B, 128>>>(scores, relev, qlen, out, D, B);
}

// round 16
// speedup vs baseline: 1.4085x; 1.1805x over previous
#include <cuda_runtime.h>

#define HLOG2E 0.7213475204444817f   // log2(e)/2
#define EPS    1e-8f

__device__ float        g_partials[8192];
__device__ unsigned int g_row_ctr;   // zero-init; last CTA resets -> replay safe
__device__ unsigned int g_done;      // zero-init; last CTA resets -> replay safe

__device__ __forceinline__ float ex2a(float x) {
    float r; asm("ex2.approx.ftz.f32 %0, %1;" : "=f"(r) : "f"(x)); return r;
}
__device__ __forceinline__ float lg2a(float x) {
    float r; asm("lg2.approx.ftz.f32 %0, %1;" : "=f"(r) : "f"(x)); return r;
}

// Pair identity: log2(sig(d)) + log2(sig(-d)) = -2*lg2(e^{d/2} + e^{-d/2}).
// Q = e^{s/2}, R = 1/Q; v_ij = Qi*Rj + Ri*Qj. Gains prescaled by 2, so the
// folded contribution of unordered pair {i,j} is -|g2i-g2j| * lg2(v_ij).
// ONE MUFU per pair.
//
// Persistent CTAs (8/SM); rows pulled from a global counter so long rows are
// dynamically balanced across SMs instead of binding per-SM makespan.

__global__ void __launch_bounds__(128, 12) ndcg_kernel(
    const float* __restrict__ scores,
    const int*   __restrict__ relev,
    const int*   __restrict__ qlen,
    float*       __restrict__ out,
    int D, int B)
{
    const int i    = threadIdx.x;       // 0..127 = D
    const int lane = i & 31;
    const int w    = i >> 5;

    __shared__ float2 s_QR[192];
    __shared__ float  s_g2[192];
    __shared__ int    s_cnt[8];
    __shared__ float  s_rn[4], s_ri[4];
    __shared__ int    s_row;
    __shared__ int    s_last;

    for (;;) {
        if (i == 0) s_row = (int)atomicAdd(&g_row_ctr, 1u);
        __syncthreads();
        const int b = s_row;
        if (b >= B) break;

        const int  L     = qlen[b];
        const bool valid = (i < L);

        const float sc = scores[b * D + i];
        const int   rv = relev[b * D + i];
        const float Q  = ex2a(sc * HLOG2E);       // e^{s/2}
        const float R  = ex2a(sc * (-HLOG2E));    // e^{-s/2}
        const float g2 = valid ? (float)(2 * ((1 << rv) - 1)) : 0.0f;

        const float2 qr = make_float2(Q, R);
        if (i < 8) s_cnt[i] = 0;
        if (valid)  { s_QR[i] = qr;     s_g2[i] = g2; }     // primary
        if (i < 64) { s_QR[L + i] = qr; s_g2[L + i] = g2; } // mirror [L, L+63]
        __syncthreads();
        if (valid) atomicAdd(&s_cnt[rv], 1);
        __syncthreads();

        // ---- pairwise sum, cyclic-distance enumeration, 2 chains ----
        float num = 0.0f;
        if (valid && L > 1) {
            const int     halfm = (L - 1) >> 1;
            const float2* bq = &s_QR[i];
            const float*  bg = &s_g2[i];
            float n0 = 0.0f, n1 = 0.0f;

            int k = 1;
            for (; k + 1 <= halfm; k += 2) {
                const float2 p0 = bq[k];
                const float2 p1 = bq[k + 1];
                const float  v0 = fmaf(Q, p0.y, R * p0.x);   // Qi*Rj + Ri*Qj
                const float  v1 = fmaf(Q, p1.y, R * p1.x);
                const float  l0 = lg2a(v0);                  // MUFU.LG2
                const float  l1 = lg2a(v1);
                const float  d0 = g2 - bg[k];
                const float  d1 = g2 - bg[k + 1];
                n0 = fmaf(-fabsf(d0), l0, n0);
                n1 = fmaf(-fabsf(d1), l1, n1);
            }
            if (k <= halfm) {
                const float2 p0 = bq[k];
                const float  v0 = fmaf(Q, p0.y, R * p0.x);
                n0 = fmaf(-fabsf(g2 - bg[k]), lg2a(v0), n0);
            }
            // tie distance k=L/2 (L even): counted once, by i < L/2 (no wrap)
            if (((L & 1) == 0) && (i < (L >> 1))) {
                const int    m  = L >> 1;
                const float2 p0 = s_QR[i + m];
                const float  v0 = fmaf(Q, p0.y, R * p0.x);
                n1 = fmaf(-fabsf(g2 - s_g2[i + m]), lg2a(v0), n1);
            }
            num = n0 + n1;
        }

        // ---- ideal DCG via counting sort (gains in {0,1,3,7,15}) ----
        float idl = 0.0f;
        if (valid) {
            const int c4 = s_cnt[4];
            const int c3 = c4 + s_cnt[3];
            const int c2 = c3 + s_cnt[2];
            const int c1 = c2 + s_cnt[1];
            float gr;
            if      (i < c4) gr = 15.0f;
            else if (i < c3) gr = 7.0f;
            else if (i < c2) gr = 3.0f;
            else if (i < c1) gr = 1.0f;
            else             gr = 0.0f;
            idl = __fdividef(gr, lg2a((float)(i + 2)));
        }

        // ---- block reduction of (num, idl) ----
        #pragma unroll
        for (int off = 16; off > 0; off >>= 1) {
            num += __shfl_down_sync(0xFFFFFFFFu, num, off);
            idl += __shfl_down_sync(0xFFFFFFFFu, idl, off);
        }
        if (lane == 0) { s_rn[w] = num; s_ri[w] = idl; }
        __syncthreads();
        if (i == 0) {
            const float n  = (s_rn[0] + s_rn[1]) + (s_rn[2] + s_rn[3]);
            const float id = (s_ri[0] + s_ri[1]) + (s_ri[2] + s_ri[3]);
            g_partials[b] = -n / (id + EPS);
        }
        __syncthreads();   // protect smem reuse on next row
    }

    // ---- completion + fused deterministic final reduction ----
    if (i == 0) {
        __threadfence();
        const unsigned int t = atomicAdd(&g_done, 1u);
        s_last = (t == (unsigned int)(gridDim.x - 1));
    }
    __syncthreads();

    if (s_last) {
        __threadfence();
        float s = 0.0f;
        for (int r = i; r < B; r += 128) s += g_partials[r];
        #pragma unroll
        for (int off = 16; off > 0; off >>= 1)
            s += __shfl_down_sync(0xFFFFFFFFu, s, off);
        if (lane == 0) s_rn[w] = s;
        __syncthreads();
        if (i == 0) {
            out[0] = ((s_rn[0] + s_rn[1]) + (s_rn[2] + s_rn[3])) / (float)B;
            g_row_ctr = 0;   // reset for next graph replay
            g_done    = 0;
        }
    }
}

extern "C" void kernel_launch(void* const* d_in, const int* in_sizes, int n_in,
                              void* d_out, int out_size)
{
    const float* scores = (const float*)d_in[0];
    const int*   relev  = (const int*)  d_in[1];
    const int*   qlen   = (const int*)  d_in[2];
    float*       out    = (float*)      d_out;

    const int B = in_sizes[2];
    const int D = in_sizes[0] / B;   // 128

    int blocks = 148 * 8;            // persistent: 8 CTAs per SM
    if (blocks > B) blocks = B;
    ndcg_kernel<<<blocks, 128>>>(scores, relev, qlen, out, D, B);
}

// round 17
// speedup vs baseline: 1.5482x; 1.0992x over previous
#include <cuda_runtime.h>

#define HLOG2E 0.7213475204444817f   // log2(e)/2
#define EPS    1e-8f

__device__ float        g_partials[8192];
__device__ unsigned int g_done;   // zero-init; last CTA resets -> graph-replay safe

__device__ __forceinline__ float ex2a(float x) {
    float r; asm("ex2.approx.ftz.f32 %0, %1;" : "=f"(r) : "f"(x)); return r;
}
__device__ __forceinline__ float lg2a(float x) {
    float r; asm("lg2.approx.ftz.f32 %0, %1;" : "=f"(r) : "f"(x)); return r;
}

// Pair identity: log2(sig(d)) + log2(sig(-d)) = -2*lg2(e^{d/2} + e^{-d/2}).
// Q = e^{s/2}, R = 1/Q; v_ij = Qi*Rj + Ri*Qj. Gains prescaled by 2, so the
// folded contribution of unordered pair {i,j} is -|g2i-g2j| * lg2(v_ij).
// ONE MUFU per pair; 4 independent chains to hide the LDS->MUFU latency.

__device__ __forceinline__ float pair1(float Q, float R, float g2,
                                       const float2* bq, const float* bg, int k) {
    const float2 p = bq[k];
    const float  v = fmaf(Q, p.y, R * p.x);    // Qi*Rj + Ri*Qj
    const float  l = lg2a(v);                  // MUFU.LG2
    return fabsf(g2 - bg[k]) * l;
}

// Block-per-row, 128 threads. Row staged as s_QR (Q,R) + s_g2 (2*gain), first
// 64 entries mirrored past L so partner index i+k never wraps. Each thread
// writes only its own slots -> one barrier before the loop.
__global__ void __launch_bounds__(128, 12) ndcg_kernel(
    const float* __restrict__ scores,
    const int*   __restrict__ relev,
    const int*   __restrict__ qlen,
    float*       __restrict__ out,
    int D, int B)
{
    const int b = blockIdx.x;
    const int i = threadIdx.x;          // 0..127 = D

    __shared__ float2 s_QR[192];
    __shared__ float  s_g2[192];
    __shared__ int    s_cnt[8];
    __shared__ float  s_rn[4], s_ri[4];
    __shared__ int    s_last;

    const int  L     = qlen[b];
    const bool valid = (i < L);

    const float sc = scores[b * D + i];
    const int   rv = relev[b * D + i];

    const float Q  = ex2a(sc * HLOG2E);       // e^{s/2}
    const float R  = ex2a(sc * (-HLOG2E));    // e^{-s/2}
    const float g2 = valid ? (float)(2 * ((1 << rv) - 1)) : 0.0f;

    const float2 qr = make_float2(Q, R);
    if (i < 8) s_cnt[i] = 0;
    if (valid)  { s_QR[i] = qr;     s_g2[i] = g2; }     // primary
    if (i < 64) { s_QR[L + i] = qr; s_g2[L + i] = g2; } // mirror [L, L+63]
    __syncthreads();
    if (valid) atomicAdd(&s_cnt[rv], 1);
    __syncthreads();

    // ---- pairwise sum, cyclic-distance enumeration, 4 independent chains ----
    float num = 0.0f;
    if (valid && L > 1) {
        const int     halfm = (L - 1) >> 1;
        const float2* bq = &s_QR[i];
        const float*  bg = &s_g2[i];
        float n0 = 0.0f, n1 = 0.0f, n2 = 0.0f, n3 = 0.0f;

        int k = 1;
        for (; k + 3 <= halfm; k += 4) {
            n0 -= pair1(Q, R, g2, bq, bg, k);
            n1 -= pair1(Q, R, g2, bq, bg, k + 1);
            n2 -= pair1(Q, R, g2, bq, bg, k + 2);
            n3 -= pair1(Q, R, g2, bq, bg, k + 3);
        }
        for (; k <= halfm; ++k)
            n0 -= pair1(Q, R, g2, bq, bg, k);

        // tie distance k=L/2 (L even): counted once, by i < L/2 (no wrap)
        if (((L & 1) == 0) && (i < (L >> 1))) {
            const int m = L >> 1;
            n1 -= pair1(Q, R, g2, &s_QR[i], &s_g2[i], m);
        }
        num = (n0 + n1) + (n2 + n3);
    }

    // ---- ideal DCG via counting sort (gains in {0,1,3,7,15}) ----
    float idl = 0.0f;
    if (valid) {
        const int c4 = s_cnt[4];
        const int c3 = c4 + s_cnt[3];
        const int c2 = c3 + s_cnt[2];
        const int c1 = c2 + s_cnt[1];
        float gr;
        if      (i < c4) gr = 15.0f;
        else if (i < c3) gr = 7.0f;
        else if (i < c2) gr = 3.0f;
        else if (i < c1) gr = 1.0f;
        else             gr = 0.0f;
        idl = __fdividef(gr, lg2a((float)(i + 2)));
    }

    // ---- block reduction of (num, idl) ----
    #pragma unroll
    for (int off = 16; off > 0; off >>= 1) {
        num += __shfl_down_sync(0xFFFFFFFFu, num, off);
        idl += __shfl_down_sync(0xFFFFFFFFu, idl, off);
    }
    const int wid  = i >> 5;
    const int lane = i & 31;
    if (lane == 0) { s_rn[wid] = num; s_ri[wid] = idl; }
    __syncthreads();
    if (i == 0) {
        const float n  = (s_rn[0] + s_rn[1]) + (s_rn[2] + s_rn[3]);
        const float id = (s_ri[0] + s_ri[1]) + (s_ri[2] + s_ri[3]);
        g_partials[b] = -n / (id + EPS);
        __threadfence();
        const unsigned int t = atomicAdd(&g_done, 1u);
        s_last = (t == (unsigned int)(gridDim.x - 1));
    }
    __syncthreads();

    // ---- last CTA: deterministic final reduction ----
    if (s_last) {
        __threadfence();
        float s = 0.0f;
        for (int r = i; r < B; r += 128) s += g_partials[r];
        #pragma unroll
        for (int off = 16; off > 0; off >>= 1)
            s += __shfl_down_sync(0xFFFFFFFFu, s, off);
        if (lane == 0) s_rn[wid] = s;
        __syncthreads();
        if (i == 0) {
            out[0] = ((s_rn[0] + s_rn[1]) + (s_rn[2] + s_rn[3])) / (float)B;
            g_done = 0;   // reset for next graph replay
        }
    }
}

extern "C" void kernel_launch(void* const* d_in, const int* in_sizes, int n_in,
                              void* d_out, int out_size)
{
    const float* scores = (const float*)d_in[0];
    const int*   relev  = (const int*)  d_in[1];
    const int*   qlen   = (const int*)  d_in[2];
    float*       out    = (float*)      d_out;

    const int B = in_sizes[2];
    const int D = in_sizes[0] / B;   // 128

    ndcg_kernel<<<B, 128>>>(scores, relev, qlen, out, D, B);
}